// round 3
// baseline (speedup 1.0000x reference)
#include <cuda_runtime.h>
#include <cuda_bf16.h>
#include <stdint.h>

#define NMAX 100000
#define EMAX 3200000
#define H1 32
#define H2 16
#define IND 128

// ---------------- scratch (device globals; no allocation allowed) ----------------
__device__ float     g_deg[NMAX];
__device__ float     g_dinv[NMAX];
__device__ int       g_cnt[NMAX];
__device__ int       g_off[NMAX + 4];
__device__ int       g_cursor[NMAX];
__device__ long long g_entries[EMAX];        // packed {norm(f32)<<32 | src}
__device__ float     g_xw1[NMAX * H1];       // x @ W1
__device__ float     g_h[NMAX * H1];         // post layer-1 (relu)
__device__ float     g_hw2[NMAX * H2];       // h @ W2

// ---------------- init ----------------
__global__ void zero_kernel(int n) {
    int i = blockIdx.x * blockDim.x + threadIdx.x;
    if (i < n) { g_deg[i] = 0.f; g_cnt[i] = 0; }
}

// ---------------- degree + count histogram ----------------
__global__ void deg_cnt_kernel(const int* __restrict__ idx,
                               const float* __restrict__ w, int E) {
    int e = blockIdx.x * blockDim.x + threadIdx.x;
    if (e >= E) return;
    int dst = idx[E + e];
    atomicAdd(&g_deg[dst], w[e]);
    atomicAdd(&g_cnt[dst], 1);
}

__global__ void dinv_kernel(int n) {
    int i = blockIdx.x * blockDim.x + threadIdx.x;
    if (i < n) g_dinv[i] = rsqrtf(g_deg[i] + 1.0f);
}

// ---------------- single-block exclusive scan (4 elems/thread/iter) ----------------
__global__ void scan_kernel(int n) {
    __shared__ int wsum[32];
    __shared__ int s_carry;
    int tid = threadIdx.x;
    if (tid == 0) s_carry = 0;
    __syncthreads();
    const int chunk = 1024 * 4;
    for (int base = 0; base < n; base += chunk) {
        int i0 = base + tid * 4;
        int4 v = make_int4(0, 0, 0, 0);
        if (i0 + 3 < n) {
            v = *reinterpret_cast<const int4*>(&g_cnt[i0]);
        } else {
            if (i0     < n) v.x = g_cnt[i0];
            if (i0 + 1 < n) v.y = g_cnt[i0 + 1];
            if (i0 + 2 < n) v.z = g_cnt[i0 + 2];
        }
        int tsum = v.x + v.y + v.z + v.w;
        int incl = tsum;
        #pragma unroll
        for (int d = 1; d < 32; d <<= 1) {
            int t = __shfl_up_sync(0xffffffffu, incl, d);
            if ((tid & 31) >= d) incl += t;
        }
        int warp = tid >> 5;
        if ((tid & 31) == 31) wsum[warp] = incl;
        __syncthreads();
        if (tid < 32) {
            int s = wsum[tid];
            #pragma unroll
            for (int d = 1; d < 32; d <<= 1) {
                int t = __shfl_up_sync(0xffffffffu, s, d);
                if (tid >= d) s += t;
            }
            wsum[tid] = s;
        }
        __syncthreads();
        int excl = incl - tsum + (warp ? wsum[warp - 1] : 0) + s_carry;
        int e0 = excl, e1 = e0 + v.x, e2 = e1 + v.y, e3 = e2 + v.z;
        if (i0 + 3 < n) {
            int4 o = make_int4(e0, e1, e2, e3);
            *reinterpret_cast<int4*>(&g_off[i0])    = o;
            *reinterpret_cast<int4*>(&g_cursor[i0]) = o;
        } else {
            if (i0     < n) { g_off[i0]     = e0; g_cursor[i0]     = e0; }
            if (i0 + 1 < n) { g_off[i0 + 1] = e1; g_cursor[i0 + 1] = e1; }
            if (i0 + 2 < n) { g_off[i0 + 2] = e2; g_cursor[i0 + 2] = e2; }
        }
        int total = wsum[31];
        __syncthreads();
        if (tid == 0) s_carry += total;
        __syncthreads();
    }
    if (tid == 0) g_off[n] = s_carry;
}

// ---------------- CSR build: scatter {src, norm} sorted by dst ----------------
__global__ void build_kernel(const int* __restrict__ idx,
                             const float* __restrict__ w, int E) {
    int e = blockIdx.x * blockDim.x + threadIdx.x;
    if (e >= E) return;
    int src = idx[e];
    int dst = idx[E + e];
    float nrm = g_dinv[src] * w[e] * g_dinv[dst];
    int pos = atomicAdd(&g_cursor[dst], 1);
    unsigned long long pk = ((unsigned long long)(unsigned)__float_as_int(nrm) << 32)
                          | (unsigned)src;
    g_entries[pos] = (long long)pk;
}

// ---------------- small dense GEMM: Y[n,M] = X[n,K] @ W[K,M] ----------------
template <int K, int M>
__global__ void gemm_kernel(const float* __restrict__ X, const float* __restrict__ W,
                            float* __restrict__ Y, int n) {
    __shared__ float Ws[K * M];
    for (int i = threadIdx.x; i < K * M; i += blockDim.x) Ws[i] = W[i];
    __syncthreads();
    int r = blockIdx.x * blockDim.x + threadIdx.x;
    if (r >= n) return;
    float acc[M];
    #pragma unroll
    for (int j = 0; j < M; j++) acc[j] = 0.f;
    const float4* X4 = reinterpret_cast<const float4*>(X) + (size_t)r * (K / 4);
    #pragma unroll 4
    for (int k4 = 0; k4 < K / 4; k4++) {
        float4 xv = __ldg(&X4[k4]);
        const float* w0 = &Ws[(k4 * 4) * M];
        #pragma unroll
        for (int j = 0; j < M; j++) {
            float s = acc[j];
            s = fmaf(xv.x, w0[j],         s);
            s = fmaf(xv.y, w0[M + j],     s);
            s = fmaf(xv.z, w0[2 * M + j], s);
            s = fmaf(xv.w, w0[3 * M + j], s);
            acc[j] = s;
        }
    }
    float4* Y4 = reinterpret_cast<float4*>(Y) + (size_t)r * (M / 4);
    #pragma unroll
    for (int j4 = 0; j4 < M / 4; j4++) {
        Y4[j4] = make_float4(acc[4 * j4], acc[4 * j4 + 1], acc[4 * j4 + 2], acc[4 * j4 + 3]);
    }
}

// ---------------- layer-1 aggregation: warp per node, 32 cols, +bias, relu ----------------
__global__ void agg32_kernel(const float* __restrict__ xw, const float* __restrict__ bias,
                             float* __restrict__ out, int n) {
    int v = (blockIdx.x * blockDim.x + threadIdx.x) >> 5;
    int lane = threadIdx.x & 31;
    if (v >= n) return;
    int beg = g_off[v], end = g_off[v + 1];
    float acc = 0.f;
    int e = beg;
    for (; e + 4 <= end; e += 4) {
        long long p0 = __ldg(&g_entries[e]);
        long long p1 = __ldg(&g_entries[e + 1]);
        long long p2 = __ldg(&g_entries[e + 2]);
        long long p3 = __ldg(&g_entries[e + 3]);
        float f0 = __ldg(&xw[(size_t)((int)(p0 & 0xffffffffLL)) * H1 + lane]);
        float f1 = __ldg(&xw[(size_t)((int)(p1 & 0xffffffffLL)) * H1 + lane]);
        float f2 = __ldg(&xw[(size_t)((int)(p2 & 0xffffffffLL)) * H1 + lane]);
        float f3 = __ldg(&xw[(size_t)((int)(p3 & 0xffffffffLL)) * H1 + lane]);
        acc = fmaf(__int_as_float((int)(p0 >> 32)), f0, acc);
        acc = fmaf(__int_as_float((int)(p1 >> 32)), f1, acc);
        acc = fmaf(__int_as_float((int)(p2 >> 32)), f2, acc);
        acc = fmaf(__int_as_float((int)(p3 >> 32)), f3, acc);
    }
    for (; e < end; e++) {
        long long p = __ldg(&g_entries[e]);
        float f = __ldg(&xw[(size_t)((int)(p & 0xffffffffLL)) * H1 + lane]);
        acc = fmaf(__int_as_float((int)(p >> 32)), f, acc);
    }
    float di = g_dinv[v];
    acc = fmaf(di * di, xw[(size_t)v * H1 + lane], acc);
    acc += bias[lane];
    acc = fmaxf(acc, 0.f);
    out[(size_t)v * H1 + lane] = acc;
}

// ---------------- layer-2 aggregation: warp per node, 16 cols, 2 edges/iter, +bias ----------------
__global__ void agg16_kernel(const float* __restrict__ hw, const float* __restrict__ bias,
                             float* __restrict__ out, int n) {
    int v = (blockIdx.x * blockDim.x + threadIdx.x) >> 5;
    int lane = threadIdx.x & 31;
    if (v >= n) return;
    int col = lane & 15;
    int sub = lane >> 4;
    int beg = g_off[v], end = g_off[v + 1];
    float acc = 0.f;
    int e = beg + sub;
    for (; e + 2 < end; e += 4) {
        long long p0 = __ldg(&g_entries[e]);
        long long p1 = __ldg(&g_entries[e + 2]);
        float f0 = __ldg(&hw[(size_t)((int)(p0 & 0xffffffffLL)) * H2 + col]);
        float f1 = __ldg(&hw[(size_t)((int)(p1 & 0xffffffffLL)) * H2 + col]);
        acc = fmaf(__int_as_float((int)(p0 >> 32)), f0, acc);
        acc = fmaf(__int_as_float((int)(p1 >> 32)), f1, acc);
    }
    for (; e < end; e += 2) {
        long long p = __ldg(&g_entries[e]);
        float f = __ldg(&hw[(size_t)((int)(p & 0xffffffffLL)) * H2 + col]);
        acc = fmaf(__int_as_float((int)(p >> 32)), f, acc);
    }
    acc += __shfl_xor_sync(0xffffffffu, acc, 16);
    float di = g_dinv[v];
    acc = fmaf(di * di, hw[(size_t)v * H2 + col], acc);
    acc += bias[col];
    if (sub == 0) out[(size_t)v * H2 + col] = acc;
}

// ---------------- launch ----------------
extern "C" void kernel_launch(void* const* d_in, const int* in_sizes, int n_in,
                              void* d_out, int out_size) {
    const float* x   = (const float*)d_in[0];
    const int*   ei  = (const int*)d_in[1];
    const float* ew  = (const float*)d_in[2];
    const float* W1  = (const float*)d_in[3];
    const float* b1  = (const float*)d_in[4];
    const float* W2  = (const float*)d_in[5];
    const float* b2  = (const float*)d_in[6];
    float*       out = (float*)d_out;

    int E = in_sizes[2];
    int n = in_sizes[0] / IND;

    float *p_xw1, *p_h, *p_hw2;
    cudaGetSymbolAddress((void**)&p_xw1, g_xw1);
    cudaGetSymbolAddress((void**)&p_h,   g_h);
    cudaGetSymbolAddress((void**)&p_hw2, g_hw2);

    int nb_n = (n + 255) / 256;
    int nb_e = (E + 255) / 256;

    zero_kernel<<<nb_n, 256>>>(n);
    deg_cnt_kernel<<<nb_e, 256>>>(ei, ew, E);
    dinv_kernel<<<nb_n, 256>>>(n);
    scan_kernel<<<1, 1024>>>(n);
    build_kernel<<<nb_e, 256>>>(ei, ew, E);

    gemm_kernel<IND, H1><<<nb_n, 256>>>(x, W1, p_xw1, n);
    agg32_kernel<<<(n * 32 + 255) / 256, 256>>>(p_xw1, b1, p_h, n);
    gemm_kernel<H1, H2><<<nb_n, 256>>>(p_h, W2, p_hw2, n);
    agg16_kernel<<<(n * 32 + 255) / 256, 256>>>(p_hw2, b2, out, n);
}

// round 4
// speedup vs baseline: 1.1040x; 1.1040x over previous
#include <cuda_runtime.h>
#include <cuda_bf16.h>
#include <stdint.h>

#define NMAX 100000
#define EMAX 3200000
#define H1 32
#define H2 16
#define IND 128
#define SCAN_TILE 4096   // 1024 threads * 4 elems
#define MAX_TILES 32     // ceil(100000/4096)=25

// ---------------- scratch (device globals; no allocation allowed) ----------------
__device__ float     g_deg[NMAX];
__device__ float     g_dinv[NMAX];
__device__ int       g_cnt[NMAX];
__device__ int       g_off[NMAX + 4];
__device__ int       g_cursor[NMAX];
__device__ int       g_bsum[MAX_TILES];
__device__ int       g_boff[MAX_TILES + 1];
__device__ long long g_entries[EMAX];        // packed {norm(f32)<<32 | src}
__device__ float     g_xw1[NMAX * H1];       // x @ W1
__device__ float     g_h[NMAX * H1];         // post layer-1 (relu)
__device__ float     g_hw2[NMAX * H2];       // h @ W2

// ---------------- init (vectorized) ----------------
__global__ void zero_kernel(int n4) {
    int i = blockIdx.x * blockDim.x + threadIdx.x;
    if (i < n4) {
        reinterpret_cast<float4*>(g_deg)[i] = make_float4(0.f, 0.f, 0.f, 0.f);
        reinterpret_cast<int4*>(g_cnt)[i]   = make_int4(0, 0, 0, 0);
    }
}

// ---------------- degree + count histogram (2 edges/thread) ----------------
__global__ void deg_cnt_kernel(const int* __restrict__ idx,
                               const float* __restrict__ w, int E) {
    int t = blockIdx.x * blockDim.x + threadIdx.x;
    int e = t * 2;
    if (e >= E) return;
    int2   d  = *reinterpret_cast<const int2*>(&idx[E + e]);
    float2 wv = *reinterpret_cast<const float2*>(&w[e]);
    atomicAdd(&g_deg[d.x], wv.x);
    atomicAdd(&g_cnt[d.x], 1);
    if (e + 1 < E) {
        atomicAdd(&g_deg[d.y], wv.y);
        atomicAdd(&g_cnt[d.y], 1);
    }
}

// ---------------- scan pass A: per-tile exclusive scan + dinv ----------------
__global__ void scanA_kernel(int n) {
    __shared__ int wsum[32];
    int tid = threadIdx.x;
    int i0 = blockIdx.x * SCAN_TILE + tid * 4;
    int4 v = make_int4(0, 0, 0, 0);
    if (i0 + 3 < n) {
        v = *reinterpret_cast<const int4*>(&g_cnt[i0]);
    } else {
        if (i0     < n) v.x = g_cnt[i0];
        if (i0 + 1 < n) v.y = g_cnt[i0 + 1];
        if (i0 + 2 < n) v.z = g_cnt[i0 + 2];
    }
    // fused dinv for same range
    if (i0 + 3 < n) {
        float4 dv = *reinterpret_cast<const float4*>(&g_deg[i0]);
        float4 rv = make_float4(rsqrtf(dv.x + 1.f), rsqrtf(dv.y + 1.f),
                                rsqrtf(dv.z + 1.f), rsqrtf(dv.w + 1.f));
        *reinterpret_cast<float4*>(&g_dinv[i0]) = rv;
    } else {
        if (i0     < n) g_dinv[i0]     = rsqrtf(g_deg[i0]     + 1.f);
        if (i0 + 1 < n) g_dinv[i0 + 1] = rsqrtf(g_deg[i0 + 1] + 1.f);
        if (i0 + 2 < n) g_dinv[i0 + 2] = rsqrtf(g_deg[i0 + 2] + 1.f);
    }
    int tsum = v.x + v.y + v.z + v.w;
    int incl = tsum;
    #pragma unroll
    for (int d = 1; d < 32; d <<= 1) {
        int t = __shfl_up_sync(0xffffffffu, incl, d);
        if ((tid & 31) >= d) incl += t;
    }
    int warp = tid >> 5;
    if ((tid & 31) == 31) wsum[warp] = incl;
    __syncthreads();
    if (tid < 32) {
        int s = wsum[tid];
        #pragma unroll
        for (int d = 1; d < 32; d <<= 1) {
            int t = __shfl_up_sync(0xffffffffu, s, d);
            if (tid >= d) s += t;
        }
        wsum[tid] = s;
    }
    __syncthreads();
    int excl = incl - tsum + (warp ? wsum[warp - 1] : 0);
    // store tile-local exclusive prefixes into g_off (finalized in pass C)
    int e0 = excl, e1 = e0 + v.x, e2 = e1 + v.y, e3 = e2 + v.z;
    if (i0 + 3 < n) {
        *reinterpret_cast<int4*>(&g_off[i0]) = make_int4(e0, e1, e2, e3);
    } else {
        if (i0     < n) g_off[i0]     = e0;
        if (i0 + 1 < n) g_off[i0 + 1] = e1;
        if (i0 + 2 < n) g_off[i0 + 2] = e2;
    }
    if (tid == 0) g_bsum[blockIdx.x] = wsum[31];
}

// ---------------- scan pass B: scan tile sums (1 warp) ----------------
__global__ void scanB_kernel(int ntiles, int n) {
    int tid = threadIdx.x;
    int s = (tid < ntiles) ? g_bsum[tid] : 0;
    int incl = s;
    #pragma unroll
    for (int d = 1; d < 32; d <<= 1) {
        int t = __shfl_up_sync(0xffffffffu, incl, d);
        if (tid >= d) incl += t;
    }
    if (tid < ntiles) g_boff[tid] = incl - s;   // exclusive
    if (tid == ntiles - 1) g_off[n] = incl;     // grand total
}

// ---------------- scan pass C: add tile offsets, write final off + cursor ----------------
__global__ void scanC_kernel(int n) {
    int i0 = (blockIdx.x * blockDim.x + threadIdx.x) * 4;
    if (i0 >= n) return;
    int boff = g_boff[i0 / SCAN_TILE];   // tile-uniform (4 elems never straddle a tile)
    if (i0 + 3 < n) {
        int4 v = *reinterpret_cast<const int4*>(&g_off[i0]);
        v.x += boff; v.y += boff; v.z += boff; v.w += boff;
        *reinterpret_cast<int4*>(&g_off[i0])    = v;
        *reinterpret_cast<int4*>(&g_cursor[i0]) = v;
    } else {
        for (int k = 0; k < 4 && i0 + k < n; k++) {
            int t = g_off[i0 + k] + boff;
            g_off[i0 + k] = t;
            g_cursor[i0 + k] = t;
        }
    }
}

// ---------------- CSR build: scatter {src, norm} sorted by dst (2 edges/thread) ----------------
__global__ void build_kernel(const int* __restrict__ idx,
                             const float* __restrict__ w, int E) {
    int t = blockIdx.x * blockDim.x + threadIdx.x;
    int e = t * 2;
    if (e >= E) return;
    int2   s  = *reinterpret_cast<const int2*>(&idx[e]);
    int2   d  = *reinterpret_cast<const int2*>(&idx[E + e]);
    float2 wv = *reinterpret_cast<const float2*>(&w[e]);
    {
        float nrm = g_dinv[s.x] * wv.x * g_dinv[d.x];
        int pos = atomicAdd(&g_cursor[d.x], 1);
        unsigned long long pk = ((unsigned long long)(unsigned)__float_as_int(nrm) << 32)
                              | (unsigned)s.x;
        g_entries[pos] = (long long)pk;
    }
    if (e + 1 < E) {
        float nrm = g_dinv[s.y] * wv.y * g_dinv[d.y];
        int pos = atomicAdd(&g_cursor[d.y], 1);
        unsigned long long pk = ((unsigned long long)(unsigned)__float_as_int(nrm) << 32)
                              | (unsigned)s.y;
        g_entries[pos] = (long long)pk;
    }
}

// ---------------- small dense GEMM: Y[n,M] = X[n,K] @ W[K,M] ----------------
template <int K, int M>
__global__ void gemm_kernel(const float* __restrict__ X, const float* __restrict__ W,
                            float* __restrict__ Y, int n) {
    __shared__ float Ws[K * M];
    for (int i = threadIdx.x; i < K * M; i += blockDim.x) Ws[i] = W[i];
    __syncthreads();
    int r = blockIdx.x * blockDim.x + threadIdx.x;
    if (r >= n) return;
    float acc[M];
    #pragma unroll
    for (int j = 0; j < M; j++) acc[j] = 0.f;
    const float4* X4 = reinterpret_cast<const float4*>(X) + (size_t)r * (K / 4);
    #pragma unroll 4
    for (int k4 = 0; k4 < K / 4; k4++) {
        float4 xv = __ldg(&X4[k4]);
        const float* w0 = &Ws[(k4 * 4) * M];
        #pragma unroll
        for (int j = 0; j < M; j++) {
            float s = acc[j];
            s = fmaf(xv.x, w0[j],         s);
            s = fmaf(xv.y, w0[M + j],     s);
            s = fmaf(xv.z, w0[2 * M + j], s);
            s = fmaf(xv.w, w0[3 * M + j], s);
            acc[j] = s;
        }
    }
    float4* Y4 = reinterpret_cast<float4*>(Y) + (size_t)r * (M / 4);
    #pragma unroll
    for (int j4 = 0; j4 < M / 4; j4++) {
        Y4[j4] = make_float4(acc[4 * j4], acc[4 * j4 + 1], acc[4 * j4 + 2], acc[4 * j4 + 3]);
    }
}

// ---------------- layer-1 aggregation: warp per node, 32 cols, +bias, relu ----------------
__global__ void agg32_kernel(const float* __restrict__ xw, const float* __restrict__ bias,
                             float* __restrict__ out, int n) {
    int v = (blockIdx.x * blockDim.x + threadIdx.x) >> 5;
    int lane = threadIdx.x & 31;
    if (v >= n) return;
    int beg = g_off[v], end = g_off[v + 1];
    float acc = 0.f;
    int e = beg;
    for (; e + 4 <= end; e += 4) {
        long long p0 = __ldg(&g_entries[e]);
        long long p1 = __ldg(&g_entries[e + 1]);
        long long p2 = __ldg(&g_entries[e + 2]);
        long long p3 = __ldg(&g_entries[e + 3]);
        float f0 = __ldg(&xw[(size_t)((int)(p0 & 0xffffffffLL)) * H1 + lane]);
        float f1 = __ldg(&xw[(size_t)((int)(p1 & 0xffffffffLL)) * H1 + lane]);
        float f2 = __ldg(&xw[(size_t)((int)(p2 & 0xffffffffLL)) * H1 + lane]);
        float f3 = __ldg(&xw[(size_t)((int)(p3 & 0xffffffffLL)) * H1 + lane]);
        acc = fmaf(__int_as_float((int)(p0 >> 32)), f0, acc);
        acc = fmaf(__int_as_float((int)(p1 >> 32)), f1, acc);
        acc = fmaf(__int_as_float((int)(p2 >> 32)), f2, acc);
        acc = fmaf(__int_as_float((int)(p3 >> 32)), f3, acc);
    }
    for (; e < end; e++) {
        long long p = __ldg(&g_entries[e]);
        float f = __ldg(&xw[(size_t)((int)(p & 0xffffffffLL)) * H1 + lane]);
        acc = fmaf(__int_as_float((int)(p >> 32)), f, acc);
    }
    float di = g_dinv[v];
    acc = fmaf(di * di, xw[(size_t)v * H1 + lane], acc);
    acc += bias[lane];
    acc = fmaxf(acc, 0.f);
    out[(size_t)v * H1 + lane] = acc;
}

// ---------------- layer-2 aggregation: warp per node, 16 cols, 2 edges/iter, +bias ----------------
__global__ void agg16_kernel(const float* __restrict__ hw, const float* __restrict__ bias,
                             float* __restrict__ out, int n) {
    int v = (blockIdx.x * blockDim.x + threadIdx.x) >> 5;
    int lane = threadIdx.x & 31;
    if (v >= n) return;
    int col = lane & 15;
    int sub = lane >> 4;
    int beg = g_off[v], end = g_off[v + 1];
    float acc = 0.f;
    int e = beg + sub;
    for (; e + 2 < end; e += 4) {
        long long p0 = __ldg(&g_entries[e]);
        long long p1 = __ldg(&g_entries[e + 2]);
        float f0 = __ldg(&hw[(size_t)((int)(p0 & 0xffffffffLL)) * H2 + col]);
        float f1 = __ldg(&hw[(size_t)((int)(p1 & 0xffffffffLL)) * H2 + col]);
        acc = fmaf(__int_as_float((int)(p0 >> 32)), f0, acc);
        acc = fmaf(__int_as_float((int)(p1 >> 32)), f1, acc);
    }
    for (; e < end; e += 2) {
        long long p = __ldg(&g_entries[e]);
        float f = __ldg(&hw[(size_t)((int)(p & 0xffffffffLL)) * H2 + col]);
        acc = fmaf(__int_as_float((int)(p >> 32)), f, acc);
    }
    acc += __shfl_xor_sync(0xffffffffu, acc, 16);
    float di = g_dinv[v];
    acc = fmaf(di * di, hw[(size_t)v * H2 + col], acc);
    acc += bias[col];
    if (sub == 0) out[(size_t)v * H2 + col] = acc;
}

// ---------------- launch ----------------
extern "C" void kernel_launch(void* const* d_in, const int* in_sizes, int n_in,
                              void* d_out, int out_size) {
    const float* x   = (const float*)d_in[0];
    const int*   ei  = (const int*)d_in[1];
    const float* ew  = (const float*)d_in[2];
    const float* W1  = (const float*)d_in[3];
    const float* b1  = (const float*)d_in[4];
    const float* W2  = (const float*)d_in[5];
    const float* b2  = (const float*)d_in[6];
    float*       out = (float*)d_out;

    int E = in_sizes[2];
    int n = in_sizes[0] / IND;

    float *p_xw1, *p_h, *p_hw2;
    cudaGetSymbolAddress((void**)&p_xw1, g_xw1);
    cudaGetSymbolAddress((void**)&p_h,   g_h);
    cudaGetSymbolAddress((void**)&p_hw2, g_hw2);

    int n4 = (n + 3) / 4;
    int nb_n = (n + 255) / 256;
    int nb_e2 = ((E + 1) / 2 + 255) / 256;
    int ntiles = (n + SCAN_TILE - 1) / SCAN_TILE;

    zero_kernel<<<(n4 + 255) / 256, 256>>>(n4);
    deg_cnt_kernel<<<nb_e2, 256>>>(ei, ew, E);
    scanA_kernel<<<ntiles, 1024>>>(n);
    scanB_kernel<<<1, 32>>>(ntiles, n);
    scanC_kernel<<<(n4 + 255) / 256, 256>>>(n);
    build_kernel<<<nb_e2, 256>>>(ei, ew, E);

    gemm_kernel<IND, H1><<<nb_n, 256>>>(x, W1, p_xw1, n);
    agg32_kernel<<<(n * 32 + 255) / 256, 256>>>(p_xw1, b1, p_h, n);
    gemm_kernel<H1, H2><<<nb_n, 256>>>(p_h, W2, p_hw2, n);
    agg16_kernel<<<(n * 32 + 255) / 256, 256>>>(p_hw2, b2, out, n);
}